// round 1
// baseline (speedup 1.0000x reference)
#include <cuda_runtime.h>
#include <math_constants.h>

// Problem constants (from reference_code)
#define BATCH        1048576
#define NUM_ANCHORS  3
#define NUM_GT       8
#define NUM_CLASSES  3
#define LAMBDA_COORD 5.0f

// Global accumulator (device scratch; no allocations allowed)
__device__ double g_sum;

__global__ void zero_accum_kernel() {
    g_sum = 0.0;
}

__device__ __forceinline__ float sigmoidf_(float x) {
    return 1.0f / (1.0f + expf(-x));
}

// One thread per batch element b. Loads:
//   preds:   24 floats (6 x float4), 96 B
//   gtboxes: 32 floats (8 x float4), 128 B
//   gtcls:   8 ints    (2 x int4),   32 B
__global__ void __launch_bounds__(256)
yolo_loss_kernel(const float* __restrict__ pred,
                 const float* __restrict__ gtb,
                 const int*   __restrict__ gtc) {
    const int b = blockIdx.x * blockDim.x + threadIdx.x;

    float local = 0.0f;

    if (b < BATCH) {
        // ---- load gt boxes for this batch element ----
        const float4* g4 = reinterpret_cast<const float4*>(gtb) + (size_t)b * NUM_GT;
        float4 g[NUM_GT];
        #pragma unroll
        for (int j = 0; j < NUM_GT; j++) g[j] = g4[j];

        // Precompute gt corners + areas (shared across the 3 anchors)
        float gx1[NUM_GT], gx2[NUM_GT], gy1[NUM_GT], gy2[NUM_GT], garea[NUM_GT];
        #pragma unroll
        for (int j = 0; j < NUM_GT; j++) {
            float gx = g[j].x, gy = g[j].y, gw = g[j].z, gh = g[j].w;
            gx1[j] = gx - gw * 0.5f;
            gx2[j] = gx + gw * 0.5f;
            gy1[j] = gy - gh * 0.5f;
            gy2[j] = gy + gh * 0.5f;
            garea[j] = (gx2[j] - gx1[j]) * (gy2[j] - gy1[j]);
        }

        // ---- load gt classes ----
        const int4* c4 = reinterpret_cast<const int4*>(gtc) + (size_t)b * 2;
        int4 c0 = c4[0];
        int4 c1 = c4[1];
        int cls[NUM_GT] = { c0.x, c0.y, c0.z, c0.w, c1.x, c1.y, c1.z, c1.w };

        // ---- load predictions: 3 anchors x 8 floats ----
        const float4* p4 = reinterpret_cast<const float4*>(pred) + (size_t)b * 6;
        float4 pv[6];
        #pragma unroll
        for (int i = 0; i < 6; i++) pv[i] = p4[i];

        #pragma unroll
        for (int a = 0; a < NUM_ANCHORS; a++) {
            // anchor layout: [x, y, w, h, conf, l0, l1, l2]
            float4 box  = pv[2 * a];       // x, y, w, h
            float4 rest = pv[2 * a + 1];   // conf, l0, l1, l2

            float px = sigmoidf_(box.x);
            float py = sigmoidf_(box.y);
            float pw = box.z;
            float ph = box.w;

            float px1 = px - pw * 0.5f;
            float px2 = px + pw * 0.5f;
            float py1 = py - ph * 0.5f;
            float py2 = py + ph * 0.5f;
            float parea = (px2 - px1) * (py2 - py1);  // mirror reference (may be negative)

            // argmax over IoU (first-max tie break => strict >)
            float best_iou = -CUDART_INF_F;
            int   best_j   = 0;
            #pragma unroll
            for (int j = 0; j < NUM_GT; j++) {
                float iw = fminf(px2, gx2[j]) - fmaxf(px1, gx1[j]);
                float ih = fminf(py2, gy2[j]) - fmaxf(py1, gy1[j]);
                iw = fmaxf(iw, 0.0f);
                ih = fmaxf(ih, 0.0f);
                float inter = iw * ih;
                float iou = inter / (parea + garea[j] - inter + 1e-6f);
                if (iou > best_iou) { best_iou = iou; best_j = j; }
            }

            bool matched = best_iou > 0.5f;
            float pconf = sigmoidf_(rest.x);

            if (matched) {
                // coord loss vs matched raw gt box (center/size form)
                float4 mb = g[best_j];
                float dx = px - mb.x;
                float dy = py - mb.y;
                float dw = pw - mb.z;
                float dh = ph - mb.w;
                float coord = dx * dx + dy * dy + dw * dw + dh * dh;

                // conf loss: -max(log(pconf), -100)
                float logp = fmaxf(logf(pconf), -100.0f);

                // class loss: NLL of log_softmax over 3 logits
                float l0 = rest.y, l1 = rest.z, l2 = rest.w;
                float m = fmaxf(l0, fmaxf(l1, l2));
                float lse = m + logf(expf(l0 - m) + expf(l1 - m) + expf(l2 - m));
                int   kc = cls[best_j];
                float lk = (kc == 0) ? l0 : ((kc == 1) ? l1 : l2);
                float nll = lse - lk;

                local += LAMBDA_COORD * coord + (-logp) + nll;
            } else {
                // conf loss for unmatched: -max(log1p(-pconf), -100)
                float log1mp = fmaxf(log1pf(-pconf), -100.0f);
                local += -log1mp;
            }
        }
    }

    // ---- block reduction ----
    // warp shuffle reduce
    #pragma unroll
    for (int off = 16; off > 0; off >>= 1)
        local += __shfl_down_sync(0xFFFFFFFFu, local, off);

    __shared__ float warp_sums[8];  // 256 threads = 8 warps
    int lane = threadIdx.x & 31;
    int wid  = threadIdx.x >> 5;
    if (lane == 0) warp_sums[wid] = local;
    __syncthreads();

    if (wid == 0) {
        float v = (lane < 8) ? warp_sums[lane] : 0.0f;
        #pragma unroll
        for (int off = 4; off > 0; off >>= 1)
            v += __shfl_down_sync(0xFFFFFFFFu, v, off);
        if (lane == 0)
            atomicAdd(&g_sum, (double)v);
    }
}

__global__ void finalize_kernel(float* __restrict__ out) {
    out[0] = (float)(g_sum / (double)BATCH);
}

extern "C" void kernel_launch(void* const* d_in, const int* in_sizes, int n_in,
                              void* d_out, int out_size) {
    const float* pred = (const float*)d_in[0];   // (B, 3, 8) f32
    const float* gtb  = (const float*)d_in[1];   // (B, 8, 4) f32
    const int*   gtc  = (const int*)d_in[2];     // (B, 8) i32
    float* out = (float*)d_out;

    zero_accum_kernel<<<1, 1>>>();
    const int threads = 256;
    const int blocks  = (BATCH + threads - 1) / threads;
    yolo_loss_kernel<<<blocks, threads>>>(pred, gtb, gtc);
    finalize_kernel<<<1, 1>>>(out);
}

// round 2
// speedup vs baseline: 1.3106x; 1.3106x over previous
#include <cuda_runtime.h>
#include <math_constants.h>

#define BATCH        1048576
#define NUM_ANCHORS  3
#define NUM_GT       8
#define LAMBDA_COORD 5.0f

#define TPB 128
// padded smem row strides (floats / ints) chosen for conflict-free LDS.128:
// lane-phase bank offsets (stride*t mod 32, t=0..7) all distinct
#define PSTR 28   // pred: 24 floats used
#define GSTR 36   // gtb : 32 floats used
#define CSTR 12   // gtc :  8 ints used

__device__ double       g_sum = 0.0;
__device__ unsigned int g_cnt = 0;

__device__ __forceinline__ float fast_sigmoid(float x) {
    return 1.0f / (1.0f + __expf(-x));
}

__global__ void __launch_bounds__(TPB)
yolo_loss_kernel(const float* __restrict__ pred,
                 const float* __restrict__ gtb,
                 const int*   __restrict__ gtc,
                 float* __restrict__ out) {
    __shared__ float sp[TPB * PSTR];   // 14 KiB
    __shared__ float sg[TPB * GSTR];   // 18 KiB
    __shared__ int   sc[TPB * CSTR];   //  6 KiB

    const int t = threadIdx.x;
    const size_t base_e = (size_t)blockIdx.x * TPB;

    // ---- coalesced staging: global -> padded smem ----
    // predictions: TPB elems * 6 float4
    {
        const float4* gp = reinterpret_cast<const float4*>(pred) + base_e * 6;
        #pragma unroll
        for (int k = 0; k < 6; k++) {
            int idx = k * TPB + t;
            float4 v = gp[idx];
            int e = idx / 6, s = idx - e * 6;
            *reinterpret_cast<float4*>(&sp[e * PSTR + s * 4]) = v;
        }
    }
    // gt boxes: TPB elems * 8 float4
    {
        const float4* gg = reinterpret_cast<const float4*>(gtb) + base_e * 8;
        #pragma unroll
        for (int k = 0; k < 8; k++) {
            int idx = k * TPB + t;
            float4 v = gg[idx];
            int e = idx >> 3, s = idx & 7;
            *reinterpret_cast<float4*>(&sg[e * GSTR + s * 4]) = v;
        }
    }
    // gt classes: TPB elems * 2 int4
    {
        const int4* gc = reinterpret_cast<const int4*>(gtc) + base_e * 2;
        #pragma unroll
        for (int k = 0; k < 2; k++) {
            int idx = k * TPB + t;
            int4 v = gc[idx];
            int e = idx >> 1, s = idx & 1;
            *reinterpret_cast<int4*>(&sc[e * CSTR + s * 4]) = v;
        }
    }
    __syncthreads();

    // ---- per-thread compute (element base_e + t) ----
    const float* myp = &sp[t * PSTR];
    const float* myg = &sg[t * GSTR];
    const int*   myc = &sc[t * CSTR];

    // gt corners + areas in registers (constant-indexed, unrolled -> no local mem)
    float gx1[NUM_GT], gx2[NUM_GT], gy1[NUM_GT], gy2[NUM_GT], garea[NUM_GT];
    #pragma unroll
    for (int j = 0; j < NUM_GT; j++) {
        float4 g = *reinterpret_cast<const float4*>(&myg[j * 4]);
        gx1[j] = g.x - g.z * 0.5f;
        gx2[j] = g.x + g.z * 0.5f;
        gy1[j] = g.y - g.w * 0.5f;
        gy2[j] = g.y + g.w * 0.5f;
        garea[j] = (gx2[j] - gx1[j]) * (gy2[j] - gy1[j]);
    }

    float local = 0.0f;

    #pragma unroll
    for (int a = 0; a < NUM_ANCHORS; a++) {
        float4 box  = *reinterpret_cast<const float4*>(&myp[a * 8]);
        float4 rest = *reinterpret_cast<const float4*>(&myp[a * 8 + 4]);

        float px = fast_sigmoid(box.x);
        float py = fast_sigmoid(box.y);
        float pw = box.z;
        float ph = box.w;

        float px1 = px - pw * 0.5f;
        float px2 = px + pw * 0.5f;
        float py1 = py - ph * 0.5f;
        float py2 = py + ph * 0.5f;
        float parea = (px2 - px1) * (py2 - py1);   // mirror reference exactly

        // argmax over IoU, first-max tie-break (strict >)
        float best_iou = -CUDART_INF_F;
        int   best_j   = 0;
        #pragma unroll
        for (int j = 0; j < NUM_GT; j++) {
            float iw = fmaxf(fminf(px2, gx2[j]) - fmaxf(px1, gx1[j]), 0.0f);
            float ih = fmaxf(fminf(py2, gy2[j]) - fmaxf(py1, gy1[j]), 0.0f);
            float inter = iw * ih;
            float iou = inter / (parea + garea[j] - inter + 1e-6f);
            if (iou > best_iou) { best_iou = iou; best_j = j; }
        }

        bool  matched = best_iou > 0.5f;
        float pconf   = fast_sigmoid(rest.x);

        if (matched) {
            // matched box / class: DYNAMIC index goes to shared memory, not regs
            float4 mb  = *reinterpret_cast<const float4*>(&myg[best_j * 4]);
            int    kc  = myc[best_j];

            float dx = px - mb.x, dy = py - mb.y;
            float dw = pw - mb.z, dh = ph - mb.w;
            float coord = dx * dx + dy * dy + dw * dw + dh * dh;

            float logp = fmaxf(__logf(pconf), -100.0f);

            float l0 = rest.y, l1 = rest.z, l2 = rest.w;
            float m   = fmaxf(l0, fmaxf(l1, l2));
            float lse = m + __logf(__expf(l0 - m) + __expf(l1 - m) + __expf(l2 - m));
            float lk  = (kc == 0) ? l0 : ((kc == 1) ? l1 : l2);

            local += LAMBDA_COORD * coord + (lse - lk) - logp;
        } else {
            float log1mp = fmaxf(__logf(1.0f - pconf), -100.0f);
            local += -log1mp;
        }
    }

    // ---- reduction: warp shuffle -> block -> one double atomic per block ----
    #pragma unroll
    for (int off = 16; off > 0; off >>= 1)
        local += __shfl_down_sync(0xFFFFFFFFu, local, off);

    __shared__ float warp_sums[TPB / 32];
    int lane = t & 31;
    int wid  = t >> 5;
    if (lane == 0) warp_sums[wid] = local;
    __syncthreads();

    if (t == 0) {
        float v = 0.0f;
        #pragma unroll
        for (int w = 0; w < TPB / 32; w++) v += warp_sums[w];
        atomicAdd(&g_sum, (double)v);

        // last-block-done: finalize + reset (keeps g_sum/g_cnt at 0 for next replay)
        __threadfence();
        unsigned int done = atomicAdd(&g_cnt, 1u);
        if (done == gridDim.x - 1) {
            out[0] = (float)(g_sum / (double)BATCH);
            g_sum = 0.0;
            g_cnt = 0u;
        }
    }
}

extern "C" void kernel_launch(void* const* d_in, const int* in_sizes, int n_in,
                              void* d_out, int out_size) {
    const float* pred = (const float*)d_in[0];   // (B, 3, 8) f32
    const float* gtb  = (const float*)d_in[1];   // (B, 8, 4) f32
    const int*   gtc  = (const int*)d_in[2];     // (B, 8) i32
    float* out = (float*)d_out;

    yolo_loss_kernel<<<BATCH / TPB, TPB>>>(pred, gtb, gtc, out);
}

// round 3
// speedup vs baseline: 2.4920x; 1.9015x over previous
#include <cuda_runtime.h>
#include <math_constants.h>

#define BATCH        1048576
#define NUM_GT       8
#define LAMBDA_COORD 5.0f
#define TPB          128          // elements per block == threads per block

// smem strides (in floats / halfwords) chosen for conflict-free access:
//  corners: 8 boxes * float4 + 16B pad = 36 floats/elem -> LDS.128 phase-conflict-free
//  areas:   8 + 1 pad = 9 floats/elem  -> 9 odd => bijective mod 32, conflict-free
#define CSTRIDE 36
#define ASTRIDE 9

__device__ double       g_sum = 0.0;
__device__ unsigned int g_cnt = 0;

__device__ __forceinline__ float fast_sigmoid(float x) {
    return __fdividef(1.0f, 1.0f + __expf(-x));
}

__global__ void __launch_bounds__(TPB, 8)
yolo_loss_kernel(const float* __restrict__ pred,
                 const float* __restrict__ gtb,
                 const int*   __restrict__ gtc,
                 float* __restrict__ out) {
    __shared__ float        sgc[TPB * CSTRIDE];   // 18.4 KB: x1,y1,x2,y2 per box
    __shared__ float        sga[TPB * ASTRIDE];   //  4.6 KB: areas
    __shared__ unsigned int scls[TPB];            //  0.5 KB: 8 classes x 4-bit nibbles

    const int    t      = threadIdx.x;
    const size_t base_e = (size_t)blockIdx.x * TPB;

    // ---- stage gt boxes: coalesced load, compute corners+area, store to smem ----
    {
        const float4* gg = reinterpret_cast<const float4*>(gtb) + base_e * NUM_GT;
        #pragma unroll
        for (int k = 0; k < NUM_GT; k++) {
            int idx = k * TPB + t;
            float4 g = gg[idx];               // cx, cy, w, h
            int e = idx >> 3, j = idx & 7;
            float hw = g.z * 0.5f, hh = g.w * 0.5f;
            float x1 = g.x - hw, x2 = g.x + hw;
            float y1 = g.y - hh, y2 = g.y + hh;
            *reinterpret_cast<float4*>(&sgc[e * CSTRIDE + j * 4]) =
                make_float4(x1, y1, x2, y2);
            sga[e * ASTRIDE + j] = (x2 - x1) * (y2 - y1);
        }
    }
    // ---- stage gt classes: pack 4 classes per u16 half (values 0..2 fit 4 bits) ----
    {
        const int4* gc = reinterpret_cast<const int4*>(gtc) + base_e * 2;
        unsigned short* s16 = reinterpret_cast<unsigned short*>(scls);
        #pragma unroll
        for (int k = 0; k < 2; k++) {
            int idx = k * TPB + t;
            int4 v = gc[idx];
            unsigned short p = (unsigned short)((v.x & 0xF) | ((v.y & 0xF) << 4) |
                                                ((v.z & 0xF) << 8) | ((v.w & 0xF) << 12));
            s16[idx] = p;   // element idx>>1, half idx&1 -> linear layout
        }
    }
    __syncthreads();

    // ---- anchor-task passes: 3 x TPB tasks cover all (element, anchor) pairs ----
    const float4* p4 = reinterpret_cast<const float4*>(pred) + base_e * 6;
    float local = 0.0f;

    #pragma unroll
    for (int pass = 0; pass < 3; pass++) {
        unsigned int task = pass * TPB + t;     // 0..383
        unsigned int e    = task / 3u;          // block-local element
        // pred float4 index for (element e, anchor a) = e*6 + a*2 = task*2
        float4 box  = p4[task * 2];             // x, y, w, h
        float4 rest = p4[task * 2 + 1];         // conf, l0, l1, l2

        float px = fast_sigmoid(box.x);
        float py = fast_sigmoid(box.y);
        float pw = box.z;
        float ph = box.w;

        float px1 = px - pw * 0.5f;
        float px2 = px + pw * 0.5f;
        float py1 = py - ph * 0.5f;
        float py2 = py + ph * 0.5f;
        float parea = (px2 - px1) * (py2 - py1);    // mirror reference exactly

        const float* cbase = &sgc[e * CSTRIDE];
        const float* abase = &sga[e * ASTRIDE];

        float best_iou = -CUDART_INF_F;
        int   best_j   = 0;
        #pragma unroll
        for (int j = 0; j < NUM_GT; j++) {
            float4 c  = *reinterpret_cast<const float4*>(&cbase[j * 4]); // x1,y1,x2,y2
            float  ga = abase[j];
            float iw = fmaxf(fminf(px2, c.z) - fmaxf(px1, c.x), 0.0f);
            float ih = fmaxf(fminf(py2, c.w) - fmaxf(py1, c.y), 0.0f);
            float inter = iw * ih;
            float iou = __fdividef(inter, parea + ga - inter + 1e-6f);
            if (iou > best_iou) { best_iou = iou; best_j = j; }
        }

        bool matched = best_iou > 0.5f;

        // conf loss via softplus on raw logit:
        //   matched:  -max(log(sigmoid(c)), -100)    = min(softplus(-c), 100)
        //   else:     -max(log1p(-sigmoid(c)), -100) = min(softplus(+c), 100)
        float s  = matched ? -rest.x : rest.x;
        float sp = fmaxf(s, 0.0f) + __logf(1.0f + __expf(-fabsf(s)));
        local += fminf(sp, 100.0f);

        if (matched) {
            // matched box: dynamic index -> shared memory (corners), reconstruct raw
            float4 mc = *reinterpret_cast<const float4*>(&cbase[best_j * 4]);
            float mbx = (mc.x + mc.z) * 0.5f;
            float mby = (mc.y + mc.w) * 0.5f;
            float mbw = mc.z - mc.x;
            float mbh = mc.w - mc.y;
            float dx = px - mbx, dy = py - mby;
            float dw = pw - mbw, dh = ph - mbh;
            float coord = dx * dx + dy * dy + dw * dw + dh * dh;

            // class NLL: logsumexp - logit[class]
            int kc = (int)((scls[e] >> (best_j * 4)) & 0xFu);
            float l0 = rest.y, l1 = rest.z, l2 = rest.w;
            float m   = fmaxf(l0, fmaxf(l1, l2));
            float lse = m + __logf(__expf(l0 - m) + __expf(l1 - m) + __expf(l2 - m));
            float lk  = (kc == 0) ? l0 : ((kc == 1) ? l1 : l2);

            local += LAMBDA_COORD * coord + (lse - lk);
        }
    }

    // ---- reduction: warp shuffle -> block -> one double atomic per block ----
    #pragma unroll
    for (int off = 16; off > 0; off >>= 1)
        local += __shfl_down_sync(0xFFFFFFFFu, local, off);

    __shared__ float warp_sums[TPB / 32];
    int lane = t & 31;
    int wid  = t >> 5;
    if (lane == 0) warp_sums[wid] = local;
    __syncthreads();

    if (t == 0) {
        float v = 0.0f;
        #pragma unroll
        for (int w = 0; w < TPB / 32; w++) v += warp_sums[w];
        atomicAdd(&g_sum, (double)v);

        __threadfence();
        unsigned int done = atomicAdd(&g_cnt, 1u);
        if (done == gridDim.x - 1) {
            out[0] = (float)(g_sum / (double)BATCH);
            g_sum = 0.0;    // reset for next graph replay
            g_cnt = 0u;
        }
    }
}

extern "C" void kernel_launch(void* const* d_in, const int* in_sizes, int n_in,
                              void* d_out, int out_size) {
    const float* pred = (const float*)d_in[0];   // (B, 3, 8) f32
    const float* gtb  = (const float*)d_in[1];   // (B, 8, 4) f32
    const int*   gtc  = (const int*)d_in[2];     // (B, 8) i32
    float* out = (float*)d_out;

    yolo_loss_kernel<<<BATCH / TPB, TPB>>>(pred, gtb, gtc, out);
}